// round 1
// baseline (speedup 1.0000x reference)
#include <cuda_runtime.h>

#define N_NODES 100000
#define NEDGES  1250000
#define D       64
#define H       8
// DH = 8, scale = 1/sqrt(8)

// Scratch (static __device__ arrays: allocation-free per harness rules)
__device__ float g_Q[N_NODES * D];
__device__ float g_K[N_NODES * D];
__device__ float g_V[N_NODES * D];
__device__ float g_Z[N_NODES * H];

// ---------------------------------------------------------------------------
// packed f32x2 FMA (Blackwell FFMA2 — only reachable via PTX fma.rn.f32x2)
// ---------------------------------------------------------------------------
__device__ __forceinline__ float2 ffma2(float2 a, float2 b, float2 c) {
    float2 d;
    asm("{\n\t"
        ".reg .b64 ra, rb, rc, rd;\n\t"
        "mov.b64 ra, {%2, %3};\n\t"
        "mov.b64 rb, {%4, %5};\n\t"
        "mov.b64 rc, {%6, %7};\n\t"
        "fma.rn.f32x2 rd, ra, rb, rc;\n\t"
        "mov.b64 {%0, %1}, rd;\n\t"
        "}"
        : "=f"(d.x), "=f"(d.y)
        : "f"(a.x), "f"(a.y), "f"(b.x), "f"(b.y), "f"(c.x), "f"(c.y));
    return d;
}

__device__ __forceinline__ void red_add_v2(float* p, float x, float y) {
    asm volatile("red.global.add.v2.f32 [%0], {%1, %2};"
                 :: "l"(p), "f"(x), "f"(y) : "memory");
}

// ---------------------------------------------------------------------------
// K1: zero output accumulator + Z accumulator
// ---------------------------------------------------------------------------
__global__ void zero_kernel(float4* __restrict__ out4) {
    int i = blockIdx.x * blockDim.x + threadIdx.x;
    float4 z = make_float4(0.f, 0.f, 0.f, 0.f);
    if (i < (N_NODES * D) / 4) out4[i] = z;
    if (i < (N_NODES * H) / 4) reinterpret_cast<float4*>(g_Z)[i] = z;
}

// ---------------------------------------------------------------------------
// K2: QKV projections. One warp per node; weights in SMEM; x row held in
// registers and broadcast via shfl; lane owns output columns (2l, 2l+1).
// ---------------------------------------------------------------------------
__global__ __launch_bounds__(256) void proj_kernel(
    const float* __restrict__ x,
    const float* __restrict__ WQ,
    const float* __restrict__ WK,
    const float* __restrict__ WV)
{
    __shared__ float sW[3][D][D];   // 48 KB exactly
    const int tid = threadIdx.x;

    const float* Ws[3] = {WQ, WK, WV};
    for (int w = 0; w < 3; w++)
        for (int i = tid; i < (D * D) / 4; i += 256)
            reinterpret_cast<float4*>(&sW[w][0][0])[i] =
                reinterpret_cast<const float4*>(Ws[w])[i];
    __syncthreads();

    const int warp = tid >> 5;
    const int lane = tid & 31;
    const int n = blockIdx.x * 8 + warp;
    if (n >= N_NODES) return;

    const float2 xr = *reinterpret_cast<const float2*>(&x[(long)n * D + 2 * lane]);

    float2 q = make_float2(0.f, 0.f);
    float2 k = make_float2(0.f, 0.f);
    float2 v = make_float2(0.f, 0.f);

#pragma unroll
    for (int i = 0; i < D; i++) {
        float xi = __shfl_sync(0xFFFFFFFFu, (i & 1) ? xr.y : xr.x, i >> 1);
        float2 xv = make_float2(xi, xi);
        q = ffma2(xv, *reinterpret_cast<const float2*>(&sW[0][i][2 * lane]), q);
        k = ffma2(xv, *reinterpret_cast<const float2*>(&sW[1][i][2 * lane]), k);
        v = ffma2(xv, *reinterpret_cast<const float2*>(&sW[2][i][2 * lane]), v);
    }

    *reinterpret_cast<float2*>(&g_Q[(long)n * D + 2 * lane]) = q;
    *reinterpret_cast<float2*>(&g_K[(long)n * D + 2 * lane]) = k;
    *reinterpret_cast<float2*>(&g_V[(long)n * D + 2 * lane]) = v;
}

// ---------------------------------------------------------------------------
// K3: fused edge kernel. 4 edges per warp. WE in SMEM (shared by block),
// ea rows staged in SMEM per warp. Per-edge:
//   Ef = ea @ WE  (f32x2 matvec, lane owns cols 2l,2l+1)
//   score_h = exp(clamp(sum_d K[src]*Q[dst]*Ef / sqrt(8), -5, 5))
//   red.add out[dst] += V[src]*score ; g_Z[dst,h] += score
// Lane l owns cols (2l, 2l+1) -> head = l >> 2 (both cols same head).
// ---------------------------------------------------------------------------
__device__ __forceinline__ float f4comp(const float4& a, int r) {
    return (r == 0) ? a.x : (r == 1) ? a.y : (r == 2) ? a.z : a.w;
}

__global__ __launch_bounds__(256) void edge_kernel(
    const float* __restrict__ ea,
    const float* __restrict__ WE,
    const int* __restrict__ ei,
    float* __restrict__ out)
{
    __shared__ float sWE[D][D];       // 16 KB
    __shared__ float sEA[8][4][D];    // 4 KB

    const int tid = threadIdx.x;
    for (int i = tid; i < (D * D) / 4; i += 256)
        reinterpret_cast<float4*>(&sWE[0][0])[i] =
            reinterpret_cast<const float4*>(WE)[i];

    const int warp = tid >> 5;
    const int lane = tid & 31;
    const long base = (long)blockIdx.x * 32 + warp * 4;

    // stage ea rows for this warp's 4 edges
#pragma unroll
    for (int e = 0; e < 4; e++) {
        long ge = base + e;
        if (ge < NEDGES) {
            float2 t = *reinterpret_cast<const float2*>(&ea[ge * D + 2 * lane]);
            *reinterpret_cast<float2*>(&sEA[warp][e][2 * lane]) = t;
        }
    }
    __syncthreads();

    // Ef matvec for 4 edges simultaneously (amortizes WE SMEM loads)
    float2 ef[4];
#pragma unroll
    for (int e = 0; e < 4; e++) ef[e] = make_float2(0.f, 0.f);

#pragma unroll
    for (int ic = 0; ic < D; ic += 4) {
        float4 a0 = *reinterpret_cast<const float4*>(&sEA[warp][0][ic]);
        float4 a1 = *reinterpret_cast<const float4*>(&sEA[warp][1][ic]);
        float4 a2 = *reinterpret_cast<const float4*>(&sEA[warp][2][ic]);
        float4 a3 = *reinterpret_cast<const float4*>(&sEA[warp][3][ic]);
#pragma unroll
        for (int r = 0; r < 4; r++) {
            float2 wv = *reinterpret_cast<const float2*>(&sWE[ic + r][2 * lane]);
            float c0 = f4comp(a0, r), c1 = f4comp(a1, r);
            float c2 = f4comp(a2, r), c3 = f4comp(a3, r);
            ef[0] = ffma2(make_float2(c0, c0), wv, ef[0]);
            ef[1] = ffma2(make_float2(c1, c1), wv, ef[1]);
            ef[2] = ffma2(make_float2(c2, c2), wv, ef[2]);
            ef[3] = ffma2(make_float2(c3, c3), wv, ef[3]);
        }
    }

    // gather indices + node vectors (issue loads early for MLP)
    int src[4], dst[4];
    float2 k2[4], q2[4], v2[4];
#pragma unroll
    for (int e = 0; e < 4; e++) {
        long ge = base + e;
        if (ge < NEDGES) {
            src[e] = ei[ge];
            dst[e] = ei[NEDGES + ge];
        }
    }
#pragma unroll
    for (int e = 0; e < 4; e++) {
        long ge = base + e;
        if (ge < NEDGES) {
            k2[e] = *reinterpret_cast<const float2*>(&g_K[(long)src[e] * D + 2 * lane]);
            q2[e] = *reinterpret_cast<const float2*>(&g_Q[(long)dst[e] * D + 2 * lane]);
            v2[e] = *reinterpret_cast<const float2*>(&g_V[(long)src[e] * D + 2 * lane]);
        }
    }

    const int head = lane >> 2;
#pragma unroll
    for (int e = 0; e < 4; e++) {
        long ge = base + e;
        if (ge >= NEDGES) continue;   // warp-uniform branch (same for all lanes)

        float p = fmaf(k2[e].y * q2[e].y, ef[e].y, (k2[e].x * q2[e].x) * ef[e].x);
        // reduce over the 4 lanes of this head (8 cols = 4 lanes)
        p += __shfl_xor_sync(0xFFFFFFFFu, p, 1, 4);
        p += __shfl_xor_sync(0xFFFFFFFFu, p, 2, 4);

        float s = p * 0.35355339059327376f;           // 1/sqrt(8)
        s = fminf(5.0f, fmaxf(-5.0f, s));
        float sc = __expf(s);

        red_add_v2(&out[(long)dst[e] * D + 2 * lane], v2[e].x * sc, v2[e].y * sc);
        if ((lane & 3) == 0)
            atomicAdd(&g_Z[(long)dst[e] * H + head], sc);
    }
}

// ---------------------------------------------------------------------------
// K4: out = wV / (Z + 1e-6)
// ---------------------------------------------------------------------------
__global__ void div_kernel(float* __restrict__ out) {
    int i = blockIdx.x * blockDim.x + threadIdx.x;   // one float2 per thread
    if (i >= (N_NODES * D) / 2) return;
    int n  = i >> 5;           // 32 float2 per node
    int c2 = i & 31;           // pair index within node; col = 2*c2
    int h  = c2 >> 2;          // head = (2*c2)/8
    float z = g_Z[n * H + h];
    float r = 1.0f / (z + 1e-6f);
    float2 v = *reinterpret_cast<float2*>(&out[(long)i * 2]);
    v.x *= r; v.y *= r;
    *reinterpret_cast<float2*>(&out[(long)i * 2]) = v;
}

// ---------------------------------------------------------------------------
extern "C" void kernel_launch(void* const* d_in, const int* in_sizes, int n_in,
                              void* d_out, int out_size)
{
    const float* x   = (const float*)d_in[0];
    const float* ea  = (const float*)d_in[1];
    const float* WQ  = (const float*)d_in[2];
    const float* WK  = (const float*)d_in[3];
    const float* WV  = (const float*)d_in[4];
    const float* WE  = (const float*)d_in[5];
    const int*   ei  = (const int*)d_in[6];
    float* out = (float*)d_out;

    (void)in_sizes; (void)n_in; (void)out_size;

    zero_kernel<<<6250, 256>>>((float4*)out);
    proj_kernel<<<(N_NODES + 7) / 8, 256>>>(x, WQ, WK, WV);
    edge_kernel<<<(NEDGES + 31) / 32, 256>>>(ea, WE, ei, out);
    div_kernel<<<(N_NODES * D / 2 + 255) / 256, 256>>>(out);
}

// round 2
// speedup vs baseline: 1.0187x; 1.0187x over previous
#include <cuda_runtime.h>

#define N_NODES 100000
#define NEDGES  1250000
#define D       64
#define H       8
// DH = 8, scale = 1/sqrt(8)

// Scratch (static __device__ arrays: allocation-free per harness rules)
__device__ float g_Q[N_NODES * D];
__device__ float g_K[N_NODES * D];
__device__ float g_V[N_NODES * D];
__device__ float g_Z[N_NODES * H];
__device__ float g_Ef[(size_t)NEDGES * D];   // 320 MB scratch for edge features

// ---------------------------------------------------------------------------
// helpers
// ---------------------------------------------------------------------------
__device__ __forceinline__ float2 ffma2(float2 a, float2 b, float2 c) {
    float2 d;
    asm("{\n\t"
        ".reg .b64 ra, rb, rc, rd;\n\t"
        "mov.b64 ra, {%2, %3};\n\t"
        "mov.b64 rb, {%4, %5};\n\t"
        "mov.b64 rc, {%6, %7};\n\t"
        "fma.rn.f32x2 rd, ra, rb, rc;\n\t"
        "mov.b64 {%0, %1}, rd;\n\t"
        "}"
        : "=f"(d.x), "=f"(d.y)
        : "f"(a.x), "f"(a.y), "f"(b.x), "f"(b.y), "f"(c.x), "f"(c.y));
    return d;
}

__device__ __forceinline__ void red_add_v4(float* p, float x, float y, float z, float w) {
    asm volatile("red.global.add.v4.f32 [%0], {%1, %2, %3, %4};"
                 :: "l"(p), "f"(x), "f"(y), "f"(z), "f"(w) : "memory");
}

__device__ __forceinline__ unsigned f2tf32(float x) {
    unsigned r;
    asm("cvt.rna.tf32.f32 %0, %1;" : "=r"(r) : "f"(x));
    return r;
}

// D += A(tf32) * B(tf32), m16n8k8
__device__ __forceinline__ void mma_tf32(float* c, const unsigned* a, const uint2& b) {
    asm volatile(
        "mma.sync.aligned.m16n8k8.row.col.f32.tf32.tf32.f32 "
        "{%0,%1,%2,%3}, {%4,%5,%6,%7}, {%8,%9}, {%0,%1,%2,%3};"
        : "+f"(c[0]), "+f"(c[1]), "+f"(c[2]), "+f"(c[3])
        : "r"(a[0]), "r"(a[1]), "r"(a[2]), "r"(a[3]), "r"(b.x), "r"(b.y));
}

// ---------------------------------------------------------------------------
// K1: zero output accumulator + Z accumulator
// ---------------------------------------------------------------------------
__global__ void zero_kernel(float4* __restrict__ out4) {
    int i = blockIdx.x * blockDim.x + threadIdx.x;
    float4 z = make_float4(0.f, 0.f, 0.f, 0.f);
    if (i < (N_NODES * D) / 4) out4[i] = z;
    if (i < (N_NODES * H) / 4) reinterpret_cast<float4*>(g_Z)[i] = z;
}

// ---------------------------------------------------------------------------
// K2: QKV projections (one warp per node, FFMA2, weights in SMEM)
// ---------------------------------------------------------------------------
__global__ __launch_bounds__(256) void proj_kernel(
    const float* __restrict__ x,
    const float* __restrict__ WQ,
    const float* __restrict__ WK,
    const float* __restrict__ WV)
{
    __shared__ float sW[3][D][D];   // 48 KB
    const int tid = threadIdx.x;

    const float* Ws[3] = {WQ, WK, WV};
    for (int w = 0; w < 3; w++)
        for (int i = tid; i < (D * D) / 4; i += 256)
            reinterpret_cast<float4*>(&sW[w][0][0])[i] =
                reinterpret_cast<const float4*>(Ws[w])[i];
    __syncthreads();

    const int warp = tid >> 5;
    const int lane = tid & 31;
    const int n = blockIdx.x * 8 + warp;
    if (n >= N_NODES) return;

    const float2 xr = *reinterpret_cast<const float2*>(&x[(long)n * D + 2 * lane]);

    float2 q = make_float2(0.f, 0.f);
    float2 k = make_float2(0.f, 0.f);
    float2 v = make_float2(0.f, 0.f);

#pragma unroll
    for (int i = 0; i < D; i++) {
        float xi = __shfl_sync(0xFFFFFFFFu, (i & 1) ? xr.y : xr.x, i >> 1);
        float2 xv = make_float2(xi, xi);
        q = ffma2(xv, *reinterpret_cast<const float2*>(&sW[0][i][2 * lane]), q);
        k = ffma2(xv, *reinterpret_cast<const float2*>(&sW[1][i][2 * lane]), k);
        v = ffma2(xv, *reinterpret_cast<const float2*>(&sW[2][i][2 * lane]), v);
    }

    *reinterpret_cast<float2*>(&g_Q[(long)n * D + 2 * lane]) = q;
    *reinterpret_cast<float2*>(&g_K[(long)n * D + 2 * lane]) = k;
    *reinterpret_cast<float2*>(&g_V[(long)n * D + 2 * lane]) = v;
}

// ---------------------------------------------------------------------------
// K3: Ef = edge_attr @ WE via tf32 tensor cores, 3-pass hi/lo split
//     (fp32-accurate: hh + hl + lh; dropped ll term ~2e-7 relative).
// Block = 256 thr = 8 warps. Each warp computes a 16x64 output tile.
// WE staged in SMEM pre-swizzled into B-fragment order (hi and lo copies).
// A-fragments loaded straight from GMEM (rows are L1-resident after first
// touch: each 16-row tile streams exactly its 4 KB once).
// ---------------------------------------------------------------------------
__global__ __launch_bounds__(256) void ef_gemm_kernel(
    const float* __restrict__ ea,
    const float* __restrict__ WE)
{
    // [ntile][kstep][lane] -> (b0, b1) = B[k*8+(l&3)][n*8+(l>>2)], B[+4 row]
    __shared__ uint2 sBh[8][8][32];   // 16 KB
    __shared__ uint2 sBl[8][8][32];   // 16 KB

    const int tid = threadIdx.x;
    for (int t = tid; t < 2048; t += 256) {
        int n = t >> 8, k = (t >> 5) & 7, l = t & 31;
        int col = n * 8 + (l >> 2);
        int r0 = k * 8 + (l & 3);
        float w0 = WE[r0 * D + col];
        float w1 = WE[(r0 + 4) * D + col];
        unsigned h0 = f2tf32(w0), h1 = f2tf32(w1);
        sBh[n][k][l] = make_uint2(h0, h1);
        sBl[n][k][l] = make_uint2(f2tf32(w0 - __uint_as_float(h0)),
                                  f2tf32(w1 - __uint_as_float(h1)));
    }
    __syncthreads();

    const int lane = tid & 31;
    const int warp = tid >> 5;
    const long row0 = (long)blockIdx.x * 128 + warp * 16 + (lane >> 2);
    const long row1 = row0 + 8;
    const bool v0 = row0 < NEDGES;
    const bool v1 = row1 < NEDGES;
    const long r0c = v0 ? row0 : 0;   // clamp for safe loads
    const long r1c = v1 ? row1 : 0;

    // A fragments for all 8 k-steps: hi and lo
    unsigned ah[8][4], al[8][4];
#pragma unroll
    for (int k = 0; k < 8; k++) {
        int c0 = k * 8 + (lane & 3);
        float a0 = v0 ? ea[r0c * D + c0]     : 0.f;
        float a1 = v1 ? ea[r1c * D + c0]     : 0.f;
        float a2 = v0 ? ea[r0c * D + c0 + 4] : 0.f;
        float a3 = v1 ? ea[r1c * D + c0 + 4] : 0.f;
        ah[k][0] = f2tf32(a0); ah[k][1] = f2tf32(a1);
        ah[k][2] = f2tf32(a2); ah[k][3] = f2tf32(a3);
        al[k][0] = f2tf32(a0 - __uint_as_float(ah[k][0]));
        al[k][1] = f2tf32(a1 - __uint_as_float(ah[k][1]));
        al[k][2] = f2tf32(a2 - __uint_as_float(ah[k][2]));
        al[k][3] = f2tf32(a3 - __uint_as_float(ah[k][3]));
    }

#pragma unroll
    for (int n = 0; n < 8; n++) {
        uint2 bh[8], bl[8];
#pragma unroll
        for (int k = 0; k < 8; k++) { bh[k] = sBh[n][k][lane]; bl[k] = sBl[n][k][lane]; }

        float c[4] = {0.f, 0.f, 0.f, 0.f};
#pragma unroll
        for (int k = 0; k < 8; k++) mma_tf32(c, ah[k], bh[k]);
#pragma unroll
        for (int k = 0; k < 8; k++) { mma_tf32(c, ah[k], bl[k]); mma_tf32(c, al[k], bh[k]); }

        int cc = n * 8 + 2 * (lane & 3);
        if (v0) *reinterpret_cast<float2*>(&g_Ef[row0 * D + cc]) = make_float2(c[0], c[1]);
        if (v1) *reinterpret_cast<float2*>(&g_Ef[row1 * D + cc]) = make_float2(c[2], c[3]);
    }
}

// ---------------------------------------------------------------------------
// K4: lean edge kernel. 16 lanes per edge (lane g owns cols 4g..4g+3,
// head = g>>1). Per warp: two half-warps, each sequentially handles 4 edges.
// score reduce over pairs via shfl(width=2); scatter via red.add.v4.
// Ef streamed with __ldcs so L2 stays dedicated to Q/K/V gathers.
// ---------------------------------------------------------------------------
__global__ __launch_bounds__(256) void edge_kernel(
    const int* __restrict__ ei,
    float* __restrict__ out)
{
    const int tid  = threadIdx.x;
    const int lane = tid & 31;
    const int warp = tid >> 5;
    const int half = lane >> 4;
    const int g    = lane & 15;
    const int head = g >> 1;

    const long base = (long)blockIdx.x * 64 + warp * 8 + half * 4;

#pragma unroll
    for (int it = 0; it < 4; it++) {
        long e = base + it;
        bool ok = e < NEDGES;
        long ec = ok ? e : 0;

        int s = __ldg(&ei[ec]);
        int d = __ldg(&ei[NEDGES + ec]);

        float4 ef = __ldcs(reinterpret_cast<const float4*>(&g_Ef[ec * D + 4 * g]));
        float4 kk = *reinterpret_cast<const float4*>(&g_K[(long)s * D + 4 * g]);
        float4 qq = *reinterpret_cast<const float4*>(&g_Q[(long)d * D + 4 * g]);
        float4 vv = *reinterpret_cast<const float4*>(&g_V[(long)s * D + 4 * g]);

        float p = (kk.x * qq.x) * ef.x;
        p = fmaf(kk.y * qq.y, ef.y, p);
        p = fmaf(kk.z * qq.z, ef.z, p);
        p = fmaf(kk.w * qq.w, ef.w, p);
        // sum the two lanes of this head (lanes 2h, 2h+1 cover its 8 cols)
        p += __shfl_xor_sync(0xFFFFFFFFu, p, 1, 2);

        float sv = p * 0.35355339059327376f;          // 1/sqrt(8)
        sv = fminf(5.0f, fmaxf(-5.0f, sv));
        float sc = __expf(sv);

        if (ok) {
            red_add_v4(&out[(long)d * D + 4 * g],
                       vv.x * sc, vv.y * sc, vv.z * sc, vv.w * sc);
            if ((g & 1) == 0)
                atomicAdd(&g_Z[(long)d * H + head], sc);
        }
    }
}

// ---------------------------------------------------------------------------
// K5: out = wV / (Z + 1e-6)
// ---------------------------------------------------------------------------
__global__ void div_kernel(float* __restrict__ out) {
    int i = blockIdx.x * blockDim.x + threadIdx.x;   // one float2 per thread
    if (i >= (N_NODES * D) / 2) return;
    int n  = i >> 5;
    int c2 = i & 31;
    int h  = c2 >> 2;
    float z = g_Z[n * H + h];
    float r = 1.0f / (z + 1e-6f);
    float2 v = *reinterpret_cast<float2*>(&out[(long)i * 2]);
    v.x *= r; v.y *= r;
    *reinterpret_cast<float2*>(&out[(long)i * 2]) = v;
}

// ---------------------------------------------------------------------------
extern "C" void kernel_launch(void* const* d_in, const int* in_sizes, int n_in,
                              void* d_out, int out_size)
{
    const float* x   = (const float*)d_in[0];
    const float* ea  = (const float*)d_in[1];
    const float* WQ  = (const float*)d_in[2];
    const float* WK  = (const float*)d_in[3];
    const float* WV  = (const float*)d_in[4];
    const float* WE  = (const float*)d_in[5];
    const int*   ei  = (const int*)d_in[6];
    float* out = (float*)d_out;

    (void)in_sizes; (void)n_in; (void)out_size;

    zero_kernel<<<6250, 256>>>((float4*)out);
    proj_kernel<<<(N_NODES + 7) / 8, 256>>>(x, WQ, WK, WV);
    ef_gemm_kernel<<<(NEDGES + 127) / 128, 256>>>(ea, WE);
    edge_kernel<<<(NEDGES + 63) / 64, 256>>>(ei, out);
    div_kernel<<<(N_NODES * D / 2 + 255) / 256, 256>>>(out);
}

// round 4
// speedup vs baseline: 1.3565x; 1.3317x over previous
#include <cuda_runtime.h>
#include <cuda_bf16.h>

#define N_NODES 100000
#define NEDGES  1250000
#define D       64
#define H       8
// DH = 8, scale = 1/sqrt(8)

// Scratch (static __device__ arrays: allocation-free per harness rules)
__device__ float g_Q[N_NODES * D];
__device__ float g_K[N_NODES * D];
__device__ float g_V[N_NODES * D];
__device__ float g_Z[N_NODES * H];

// ---------------------------------------------------------------------------
// helpers
// ---------------------------------------------------------------------------
__device__ __forceinline__ float2 ffma2(float2 a, float2 b, float2 c) {
    float2 d;
    asm("{\n\t"
        ".reg .b64 ra, rb, rc, rd;\n\t"
        "mov.b64 ra, {%2, %3};\n\t"
        "mov.b64 rb, {%4, %5};\n\t"
        "mov.b64 rc, {%6, %7};\n\t"
        "fma.rn.f32x2 rd, ra, rb, rc;\n\t"
        "mov.b64 {%0, %1}, rd;\n\t"
        "}"
        : "=f"(d.x), "=f"(d.y)
        : "f"(a.x), "f"(a.y), "f"(b.x), "f"(b.y), "f"(c.x), "f"(c.y));
    return d;
}

__device__ __forceinline__ void red_add_v4(float* p, float x, float y, float z, float w) {
    asm volatile("red.global.add.v4.f32 [%0], {%1, %2, %3, %4};"
                 :: "l"(p), "f"(x), "f"(y), "f"(z), "f"(w) : "memory");
}

// split a float2 into hi/lo packed bf16x2 (hi + lo recovers ~16 mantissa bits)
__device__ __forceinline__ void split_bf16x2(float2 v, unsigned& h, unsigned& l) {
    __nv_bfloat162 hb = __floats2bfloat162_rn(v.x, v.y);
    float hx = __bfloat162float(__low2bfloat16(hb));
    float hy = __bfloat162float(__high2bfloat16(hb));
    __nv_bfloat162 lb = __floats2bfloat162_rn(v.x - hx, v.y - hy);
    h = *reinterpret_cast<unsigned*>(&hb);
    l = *reinterpret_cast<unsigned*>(&lb);
}

// D += A(bf16) * B(bf16), m16n8k16, f32 accumulate
__device__ __forceinline__ void mma_bf16(float* c, const unsigned* a,
                                         unsigned b0, unsigned b1) {
    asm volatile(
        "mma.sync.aligned.m16n8k16.row.col.f32.bf16.bf16.f32 "
        "{%0,%1,%2,%3}, {%4,%5,%6,%7}, {%8,%9}, {%0,%1,%2,%3};"
        : "+f"(c[0]), "+f"(c[1]), "+f"(c[2]), "+f"(c[3])
        : "r"(a[0]), "r"(a[1]), "r"(a[2]), "r"(a[3]), "r"(b0), "r"(b1));
}

// ---------------------------------------------------------------------------
// K1: QKV projections (one warp per node, FFMA2, weights in SMEM).
// Also zeroes this node's output row and Z row (replaces zero_kernel).
// ---------------------------------------------------------------------------
__global__ __launch_bounds__(256) void proj_kernel(
    const float* __restrict__ x,
    const float* __restrict__ WQ,
    const float* __restrict__ WK,
    const float* __restrict__ WV,
    float* __restrict__ out)
{
    __shared__ float sW[3][D][D];   // 48 KB
    const int tid = threadIdx.x;

    const float* Ws[3] = {WQ, WK, WV};
    for (int w = 0; w < 3; w++)
        for (int i = tid; i < (D * D) / 4; i += 256)
            reinterpret_cast<float4*>(&sW[w][0][0])[i] =
                __ldg(&reinterpret_cast<const float4*>(Ws[w])[i]);
    __syncthreads();

    const int warp = tid >> 5;
    const int lane = tid & 31;
    const int n = blockIdx.x * 8 + warp;
    if (n >= N_NODES) return;

    const float2 xr = __ldg(reinterpret_cast<const float2*>(&x[(long)n * D + 2 * lane]));

    float2 q = make_float2(0.f, 0.f);
    float2 k = make_float2(0.f, 0.f);
    float2 v = make_float2(0.f, 0.f);

#pragma unroll
    for (int i = 0; i < D; i++) {
        float xi = __shfl_sync(0xFFFFFFFFu, (i & 1) ? xr.y : xr.x, i >> 1);
        float2 xv = make_float2(xi, xi);
        q = ffma2(xv, *reinterpret_cast<const float2*>(&sW[0][i][2 * lane]), q);
        k = ffma2(xv, *reinterpret_cast<const float2*>(&sW[1][i][2 * lane]), k);
        v = ffma2(xv, *reinterpret_cast<const float2*>(&sW[2][i][2 * lane]), v);
    }

    *reinterpret_cast<float2*>(&g_Q[(long)n * D + 2 * lane]) = q;
    *reinterpret_cast<float2*>(&g_K[(long)n * D + 2 * lane]) = k;
    *reinterpret_cast<float2*>(&g_V[(long)n * D + 2 * lane]) = v;

    // zero accumulators for this node
    *reinterpret_cast<float2*>(&out[(long)n * D + 2 * lane]) = make_float2(0.f, 0.f);
    if (lane < H) g_Z[n * H + lane] = 0.f;
}

// ---------------------------------------------------------------------------
// K2: FUSED edge kernel. Per warp = 16 edges.
//  Phase A: Ef tile = ea[16x64] @ WE via bf16 split mma (hh + hl + lh),
//           96x m16n8k16 per warp-tile, -> per-warp SMEM tile (XOR swizzled).
//  Phase B: edge phase: 16 lanes/edge (lane g owns cols 4g..4g+3,
//           head g>>1), Ef from SMEM, K/Q/V gathered from L2,
//           score -> red.add.v4 scatter + Z atomic.
// NEDGES % 16 == 0 -> every live warp-tile is full (no per-edge predicates).
// ---------------------------------------------------------------------------
__global__ __launch_bounds__(256) void fused_edge_kernel(
    const float* __restrict__ ea,
    const float* __restrict__ WE,
    const int* __restrict__ ei,
    float* __restrict__ out)
{
    // B fragments: [ntile][kstep][lane] = (bh0, bh1, bl0, bl1)
    __shared__ uint4 sB[8][4][32];     // 16 KB
    __shared__ float sEf[8][16][64];   // 32 KB (per-warp 16x64 Ef tiles)

    const int tid = threadIdx.x;

    // --- stage WE as packed bf16 hi/lo B-fragments ---
    for (int t = tid; t < 1024; t += 256) {
        int n = t >> 7, k = (t >> 5) & 3, l = t & 31;
        int tig = l & 3, grp = l >> 2;
        int col = n * 8 + grp;
        int r0 = k * 16 + 2 * tig;
        float2 w0 = make_float2(__ldg(&WE[r0 * D + col]),       __ldg(&WE[(r0 + 1) * D + col]));
        float2 w1 = make_float2(__ldg(&WE[(r0 + 8) * D + col]), __ldg(&WE[(r0 + 9) * D + col]));
        unsigned h0, l0, h1, l1;
        split_bf16x2(w0, h0, l0);
        split_bf16x2(w1, h1, l1);
        sB[n][k][l] = make_uint4(h0, h1, l0, l1);
    }
    __syncthreads();

    const int warp = tid >> 5;
    const int lane = tid & 31;
    const int base = (blockIdx.x * 8 + warp) * 16;
    if (base >= NEDGES) return;   // tail warps (only block-wide sync is above)

    const int grp = lane >> 2;    // 0..7  (row within tile)
    const int tig = lane & 3;     // 0..3  (col pair)
    const long row0 = base + grp;
    const long row1 = row0 + 8;

    // --- A fragments (16 x LDG.64, fully-consumed 32B sectors) ---
    unsigned Ah[4][4], Al[4][4];
#pragma unroll
    for (int k = 0; k < 4; k++) {
        float2 x0 = __ldg(reinterpret_cast<const float2*>(ea + row0 * D + k * 16 + 2 * tig));
        float2 x1 = __ldg(reinterpret_cast<const float2*>(ea + row1 * D + k * 16 + 2 * tig));
        float2 x2 = __ldg(reinterpret_cast<const float2*>(ea + row0 * D + k * 16 + 8 + 2 * tig));
        float2 x3 = __ldg(reinterpret_cast<const float2*>(ea + row1 * D + k * 16 + 8 + 2 * tig));
        split_bf16x2(x0, Ah[k][0], Al[k][0]);
        split_bf16x2(x1, Ah[k][1], Al[k][1]);
        split_bf16x2(x2, Ah[k][2], Al[k][2]);
        split_bf16x2(x3, Ah[k][3], Al[k][3]);
    }

    // --- 8 n-tiles: 12 mma each, 3 independent accumulator chains ---
    const int swz = (grp & 7) << 3;   // XOR swizzle (consistent for row, row+8)
#pragma unroll
    for (int n = 0; n < 8; n++) {
        uint4 b[4];
#pragma unroll
        for (int k = 0; k < 4; k++) b[k] = sB[n][k][lane];

        float c1[4] = {0.f, 0.f, 0.f, 0.f};
        float c2[4] = {0.f, 0.f, 0.f, 0.f};
        float c3[4] = {0.f, 0.f, 0.f, 0.f};
#pragma unroll
        for (int k = 0; k < 4; k++) {
            mma_bf16(c1, Ah[k], b[k].x, b[k].y);   // hh
            mma_bf16(c2, Ah[k], b[k].z, b[k].w);   // h*l
            mma_bf16(c3, Al[k], b[k].x, b[k].y);   // l*h
        }

        int colw = (8 * n + 2 * tig) ^ swz;
        *reinterpret_cast<float2*>(&sEf[warp][grp][colw]) =
            make_float2(c1[0] + c2[0] + c3[0], c1[1] + c2[1] + c3[1]);
        *reinterpret_cast<float2*>(&sEf[warp][grp + 8][colw]) =
            make_float2(c1[2] + c2[2] + c3[2], c1[3] + c2[3] + c3[3]);
    }

    // --- preload src (lanes 0-15) / dst (lanes 16-31) for the 16 edges ---
    int sd = __ldg(&ei[(lane >> 4) * NEDGES + base + (lane & 15)]);
    __syncwarp();

    // --- edge phase: two half-warps, 8 iterations, 16 lanes per edge ---
    const int half = lane >> 4;
    const int g = lane & 15;
#pragma unroll
    for (int it = 0; it < 8; it++) {
        int r = it * 2 + half;
        int s = __shfl_sync(0xFFFFFFFFu, sd, r);
        int d = __shfl_sync(0xFFFFFFFFu, sd, 16 + r);

        float4 ef = *reinterpret_cast<const float4*>(
            &sEf[warp][r][(4 * g) ^ ((r & 7) << 3)]);
        float4 kk = *reinterpret_cast<const float4*>(&g_K[s * D + 4 * g]);
        float4 qq = *reinterpret_cast<const float4*>(&g_Q[d * D + 4 * g]);
        float4 vv = *reinterpret_cast<const float4*>(&g_V[s * D + 4 * g]);

        float p = (kk.x * qq.x) * ef.x;
        p = fmaf(kk.y * qq.y, ef.y, p);
        p = fmaf(kk.z * qq.z, ef.z, p);
        p = fmaf(kk.w * qq.w, ef.w, p);
        p += __shfl_xor_sync(0xFFFFFFFFu, p, 1);   // pair covers the head's 8 cols

        float sv = p * 0.35355339059327376f;       // 1/sqrt(8)
        sv = fminf(5.0f, fmaxf(-5.0f, sv));
        float sc = __expf(sv);

        red_add_v4(&out[(long)d * D + 4 * g],
                   vv.x * sc, vv.y * sc, vv.z * sc, vv.w * sc);
        if ((g & 1) == 0)
            atomicAdd(&g_Z[d * H + (g >> 1)], sc);
    }
}

// ---------------------------------------------------------------------------
// K3: out = wV / (Z + 1e-6)   (one float4 per thread)
// ---------------------------------------------------------------------------
__global__ void div_kernel(float4* __restrict__ out4) {
    int i = blockIdx.x * blockDim.x + threadIdx.x;
    if (i >= (N_NODES * D) / 4) return;
    int n  = i >> 4;           // 16 float4 per node
    int c4 = i & 15;
    int h  = c4 >> 1;          // head = (4*c4)/8
    float r = 1.0f / (g_Z[n * H + h] + 1e-6f);
    float4 v = out4[i];
    v.x *= r; v.y *= r; v.z *= r; v.w *= r;
    out4[i] = v;
}

// ---------------------------------------------------------------------------
extern "C" void kernel_launch(void* const* d_in, const int* in_sizes, int n_in,
                              void* d_out, int out_size)
{
    const float* x   = (const float*)d_in[0];
    const float* ea  = (const float*)d_in[1];
    const float* WQ  = (const float*)d_in[2];
    const float* WK  = (const float*)d_in[3];
    const float* WV  = (const float*)d_in[4];
    const float* WE  = (const float*)d_in[5];
    const int*   ei  = (const int*)d_in[6];
    float* out = (float*)d_out;

    (void)in_sizes; (void)n_in; (void)out_size;

    proj_kernel<<<(N_NODES + 7) / 8, 256>>>(x, WQ, WK, WV, out);
    fused_edge_kernel<<<(NEDGES / 16 + 7) / 8, 256>>>(ea, WE, ei, out);
    div_kernel<<<(N_NODES * D / 4 + 255) / 256, 256>>>((float4*)out);
}

// round 5
// speedup vs baseline: 2.0314x; 1.4976x over previous
#include <cuda_runtime.h>
#include <cuda_bf16.h>

#define N_NODES 100000
#define NEDGES  1250000
#define D       64
#define H       8
// DH = 8, scale = 1/sqrt(8)

// Scratch (static __device__ arrays: allocation-free per harness rules)
__device__ float g_Q[N_NODES * D];
__device__ float g_K[N_NODES * D];
__device__ float g_V[N_NODES * D];
__device__ float g_Z[N_NODES * H];

// ---------------------------------------------------------------------------
// helpers
// ---------------------------------------------------------------------------
__device__ __forceinline__ void red_add_v4(float* p, float x, float y, float z, float w) {
    asm volatile("red.global.add.v4.f32 [%0], {%1, %2, %3, %4};"
                 :: "l"(p), "f"(x), "f"(y), "f"(z), "f"(w) : "memory");
}

// split a float2 into hi/lo packed bf16x2 (hi + lo recovers ~16 mantissa bits)
__device__ __forceinline__ void split_bf16x2(float2 v, unsigned& h, unsigned& l) {
    __nv_bfloat162 hb = __floats2bfloat162_rn(v.x, v.y);
    float hx = __bfloat162float(__low2bfloat16(hb));
    float hy = __bfloat162float(__high2bfloat16(hb));
    __nv_bfloat162 lb = __floats2bfloat162_rn(v.x - hx, v.y - hy);
    h = *reinterpret_cast<unsigned*>(&hb);
    l = *reinterpret_cast<unsigned*>(&lb);
}

// D += A(bf16) * B(bf16), m16n8k16, f32 accumulate
__device__ __forceinline__ void mma_bf16(float* c, const unsigned* a,
                                         unsigned b0, unsigned b1) {
    asm volatile(
        "mma.sync.aligned.m16n8k16.row.col.f32.bf16.bf16.f32 "
        "{%0,%1,%2,%3}, {%4,%5,%6,%7}, {%8,%9}, {%0,%1,%2,%3};"
        : "+f"(c[0]), "+f"(c[1]), "+f"(c[2]), "+f"(c[3])
        : "r"(a[0]), "r"(a[1]), "r"(a[2]), "r"(a[3]), "r"(b0), "r"(b1));
}

// ---------------------------------------------------------------------------
// K1: QKV projections via bf16-split tensor-core mma (hh + hl + lh).
// One warp per 16 nodes. All 3 weight matrices staged in SMEM as pre-swizzled
// hi/lo bf16 B-fragments (48 KB). Also zeroes out[] rows and g_Z rows.
// N_NODES % 16 == 0 -> warp tiles are full or fully inactive.
// ---------------------------------------------------------------------------
__global__ __launch_bounds__(256) void proj_kernel(
    const float* __restrict__ x,
    const float* __restrict__ WQ,
    const float* __restrict__ WK,
    const float* __restrict__ WV,
    float* __restrict__ out)
{
    // [mat][ntile][kstep][lane] = (bh0, bh1, bl0, bl1)
    __shared__ uint4 sB[3][8][4][32];   // 48 KB

    const int tid = threadIdx.x;
    const float* Ws[3] = {WQ, WK, WV};
    for (int t = tid; t < 3 * 1024; t += 256) {
        int w = t >> 10, rem = t & 1023;
        int n = rem >> 7, k = (rem >> 5) & 3, l = rem & 31;
        int tig = l & 3, grp = l >> 2;
        int col = n * 8 + grp;
        int r0 = k * 16 + 2 * tig;
        const float* W = Ws[w];
        float2 w0 = make_float2(__ldg(&W[r0 * D + col]),       __ldg(&W[(r0 + 1) * D + col]));
        float2 w1 = make_float2(__ldg(&W[(r0 + 8) * D + col]), __ldg(&W[(r0 + 9) * D + col]));
        unsigned h0, l0, h1, l1;
        split_bf16x2(w0, h0, l0);
        split_bf16x2(w1, h1, l1);
        sB[w][n][k][l] = make_uint4(h0, h1, l0, l1);
    }
    __syncthreads();

    const int warp = tid >> 5;
    const int lane = tid & 31;
    const int tile = blockIdx.x * 8 + warp;     // 16-node tile index
    if (tile >= N_NODES / 16) return;

    const int grp = lane >> 2;    // 0..7
    const int tig = lane & 3;     // 0..3
    const long row0 = (long)tile * 16 + grp;
    const long row1 = row0 + 8;

    // --- A fragments from x (hi/lo split) ---
    unsigned Ah[4][4], Al[4][4];
#pragma unroll
    for (int k = 0; k < 4; k++) {
        float2 x0 = __ldg(reinterpret_cast<const float2*>(x + row0 * D + k * 16 + 2 * tig));
        float2 x1 = __ldg(reinterpret_cast<const float2*>(x + row1 * D + k * 16 + 2 * tig));
        float2 x2 = __ldg(reinterpret_cast<const float2*>(x + row0 * D + k * 16 + 8 + 2 * tig));
        float2 x3 = __ldg(reinterpret_cast<const float2*>(x + row1 * D + k * 16 + 8 + 2 * tig));
        split_bf16x2(x0, Ah[k][0], Al[k][0]);
        split_bf16x2(x1, Ah[k][1], Al[k][1]);
        split_bf16x2(x2, Ah[k][2], Al[k][2]);
        split_bf16x2(x3, Ah[k][3], Al[k][3]);
    }

    float* Outs[3] = {g_Q, g_K, g_V};
#pragma unroll
    for (int w = 0; w < 3; w++) {
        float* O = Outs[w];
#pragma unroll
        for (int n = 0; n < 8; n++) {
            uint4 b[4];
#pragma unroll
            for (int k = 0; k < 4; k++) b[k] = sB[w][n][k][lane];

            float c1[4] = {0.f, 0.f, 0.f, 0.f};
            float c2[4] = {0.f, 0.f, 0.f, 0.f};
            float c3[4] = {0.f, 0.f, 0.f, 0.f};
#pragma unroll
            for (int k = 0; k < 4; k++) {
                mma_bf16(c1, Ah[k], b[k].x, b[k].y);   // hh
                mma_bf16(c2, Ah[k], b[k].z, b[k].w);   // h*l
                mma_bf16(c3, Al[k], b[k].x, b[k].y);   // l*h
            }

            int cc = n * 8 + 2 * tig;
            *reinterpret_cast<float2*>(&O[row0 * D + cc]) =
                make_float2(c1[0] + c2[0] + c3[0], c1[1] + c2[1] + c3[1]);
            *reinterpret_cast<float2*>(&O[row1 * D + cc]) =
                make_float2(c1[2] + c2[2] + c3[2], c1[3] + c2[3] + c3[3]);
        }
    }

    // --- zero accumulators for these 16 nodes ---
    float4 z4 = make_float4(0.f, 0.f, 0.f, 0.f);
    float4* o4 = reinterpret_cast<float4*>(out) + (long)tile * 256;  // 16 rows * 16 f4
#pragma unroll
    for (int i = 0; i < 8; i++) o4[i * 32 + lane] = z4;
    reinterpret_cast<float4*>(g_Z)[(long)tile * 32 + lane] = z4;
}

// ---------------------------------------------------------------------------
// K2: FUSED edge kernel. Per warp = 16 edges.
//  Phase A: Ef tile = ea[16x64] @ WE via bf16 split mma (hh + hl + lh),
//           96x m16n8k16 per warp-tile, -> per-warp SMEM tile (XOR swizzled).
//  Phase B: edge phase: 16 lanes/edge (lane g owns cols 4g..4g+3,
//           head g>>1), Ef from SMEM, K/Q/V gathered from L2,
//           score -> red.add.v4 scatter + Z atomic.
// NEDGES % 16 == 0 -> every live warp-tile is full (no per-edge predicates).
// ---------------------------------------------------------------------------
__global__ __launch_bounds__(256) void fused_edge_kernel(
    const float* __restrict__ ea,
    const float* __restrict__ WE,
    const int* __restrict__ ei,
    float* __restrict__ out)
{
    // B fragments: [ntile][kstep][lane] = (bh0, bh1, bl0, bl1)
    __shared__ uint4 sB[8][4][32];     // 16 KB
    __shared__ float sEf[8][16][64];   // 32 KB (per-warp 16x64 Ef tiles)

    const int tid = threadIdx.x;

    // --- stage WE as packed bf16 hi/lo B-fragments ---
    for (int t = tid; t < 1024; t += 256) {
        int n = t >> 7, k = (t >> 5) & 3, l = t & 31;
        int tig = l & 3, grp = l >> 2;
        int col = n * 8 + grp;
        int r0 = k * 16 + 2 * tig;
        float2 w0 = make_float2(__ldg(&WE[r0 * D + col]),       __ldg(&WE[(r0 + 1) * D + col]));
        float2 w1 = make_float2(__ldg(&WE[(r0 + 8) * D + col]), __ldg(&WE[(r0 + 9) * D + col]));
        unsigned h0, l0, h1, l1;
        split_bf16x2(w0, h0, l0);
        split_bf16x2(w1, h1, l1);
        sB[n][k][l] = make_uint4(h0, h1, l0, l1);
    }
    __syncthreads();

    const int warp = tid >> 5;
    const int lane = tid & 31;
    const int base = (blockIdx.x * 8 + warp) * 16;
    if (base >= NEDGES) return;   // tail warps (only block-wide sync is above)

    // --- preload src (lanes 0-15) / dst (lanes 16-31) for the 16 edges ---
    int sd = __ldg(&ei[(lane >> 4) * NEDGES + base + (lane & 15)]);

    const int grp = lane >> 2;    // 0..7  (row within tile)
    const int tig = lane & 3;     // 0..3  (col pair)
    const long row0 = base + grp;
    const long row1 = row0 + 8;

    // --- A fragments (16 x LDG.64, fully-consumed 32B sectors) ---
    unsigned Ah[4][4], Al[4][4];
#pragma unroll
    for (int k = 0; k < 4; k++) {
        float2 x0 = __ldg(reinterpret_cast<const float2*>(ea + row0 * D + k * 16 + 2 * tig));
        float2 x1 = __ldg(reinterpret_cast<const float2*>(ea + row1 * D + k * 16 + 2 * tig));
        float2 x2 = __ldg(reinterpret_cast<const float2*>(ea + row0 * D + k * 16 + 8 + 2 * tig));
        float2 x3 = __ldg(reinterpret_cast<const float2*>(ea + row1 * D + k * 16 + 8 + 2 * tig));
        split_bf16x2(x0, Ah[k][0], Al[k][0]);
        split_bf16x2(x1, Ah[k][1], Al[k][1]);
        split_bf16x2(x2, Ah[k][2], Al[k][2]);
        split_bf16x2(x3, Ah[k][3], Al[k][3]);
    }

    // --- 8 n-tiles: 12 mma each, 3 independent accumulator chains ---
    const int swz = (grp & 7) << 3;   // XOR swizzle (consistent for row, row+8)
#pragma unroll
    for (int n = 0; n < 8; n++) {
        uint4 b[4];
#pragma unroll
        for (int k = 0; k < 4; k++) b[k] = sB[n][k][lane];

        float c1[4] = {0.f, 0.f, 0.f, 0.f};
        float c2[4] = {0.f, 0.f, 0.f, 0.f};
        float c3[4] = {0.f, 0.f, 0.f, 0.f};
#pragma unroll
        for (int k = 0; k < 4; k++) {
            mma_bf16(c1, Ah[k], b[k].x, b[k].y);   // hh
            mma_bf16(c2, Ah[k], b[k].z, b[k].w);   // h*l
            mma_bf16(c3, Al[k], b[k].x, b[k].y);   // l*h
        }

        int colw = (8 * n + 2 * tig) ^ swz;
        *reinterpret_cast<float2*>(&sEf[warp][grp][colw]) =
            make_float2(c1[0] + c2[0] + c3[0], c1[1] + c2[1] + c3[1]);
        *reinterpret_cast<float2*>(&sEf[warp][grp + 8][colw]) =
            make_float2(c1[2] + c2[2] + c3[2], c1[3] + c2[3] + c3[3]);
    }
    __syncwarp();

    // --- edge phase: two half-warps, 8 iterations, 16 lanes per edge ---
    const int half = lane >> 4;
    const int g = lane & 15;
#pragma unroll
    for (int it = 0; it < 8; it++) {
        int r = it * 2 + half;
        int s = __shfl_sync(0xFFFFFFFFu, sd, r);
        int d = __shfl_sync(0xFFFFFFFFu, sd, 16 + r);

        float4 ef = *reinterpret_cast<const float4*>(
            &sEf[warp][r][(4 * g) ^ ((r & 7) << 3)]);
        float4 kk = *reinterpret_cast<const float4*>(&g_K[s * D + 4 * g]);
        float4 qq = *reinterpret_cast<const float4*>(&g_Q[d * D + 4 * g]);
        float4 vv = *reinterpret_cast<const float4*>(&g_V[s * D + 4 * g]);

        float p = (kk.x * qq.x) * ef.x;
        p = fmaf(kk.y * qq.y, ef.y, p);
        p = fmaf(kk.z * qq.z, ef.z, p);
        p = fmaf(kk.w * qq.w, ef.w, p);
        p += __shfl_xor_sync(0xFFFFFFFFu, p, 1);   // pair covers the head's 8 cols

        float sv = p * 0.35355339059327376f;       // 1/sqrt(8)
        sv = fminf(5.0f, fmaxf(-5.0f, sv));
        float sc = __expf(sv);

        red_add_v4(&out[(long)d * D + 4 * g],
                   vv.x * sc, vv.y * sc, vv.z * sc, vv.w * sc);
        if ((g & 1) == 0)
            atomicAdd(&g_Z[d * H + (g >> 1)], sc);
    }
}

// ---------------------------------------------------------------------------
// K3: out = wV / (Z + 1e-6)   (one float4 per thread)
// ---------------------------------------------------------------------------
__global__ void div_kernel(float4* __restrict__ out4) {
    int i = blockIdx.x * blockDim.x + threadIdx.x;
    if (i >= (N_NODES * D) / 4) return;
    int n  = i >> 4;           // 16 float4 per node
    int c4 = i & 15;
    int h  = c4 >> 1;          // head = (4*c4)/8
    float r = 1.0f / (g_Z[n * H + h] + 1e-6f);
    float4 v = out4[i];
    v.x *= r; v.y *= r; v.z *= r; v.w *= r;
    out4[i] = v;
}

// ---------------------------------------------------------------------------
extern "C" void kernel_launch(void* const* d_in, const int* in_sizes, int n_in,
                              void* d_out, int out_size)
{
    const float* x   = (const float*)d_in[0];
    const float* ea  = (const float*)d_in[1];
    const float* WQ  = (const float*)d_in[2];
    const float* WK  = (const float*)d_in[3];
    const float* WV  = (const float*)d_in[4];
    const float* WE  = (const float*)d_in[5];
    const int*   ei  = (const int*)d_in[6];
    float* out = (float*)d_out;

    (void)in_sizes; (void)n_in; (void)out_size;

    proj_kernel<<<(N_NODES / 16 + 7) / 8, 256>>>(x, WQ, WK, WV, out);
    fused_edge_kernel<<<(NEDGES / 16 + 7) / 8, 256>>>(ea, WE, ei, out);
    div_kernel<<<(N_NODES * D / 4 + 255) / 256, 256>>>((float4*)out);
}

// round 6
// speedup vs baseline: 2.4116x; 1.1872x over previous
#include <cuda_runtime.h>
#include <cuda_fp16.h>

#define N_NODES 100000
#define NEDGES  1250000
#define D       64
#define H       8
// DH = 8, scale = 1/sqrt(8)

// Scratch (static __device__ arrays: allocation-free per harness rules)
__device__ float g_Q[N_NODES * D];
__device__ float g_K[N_NODES * D];
__device__ float g_V[N_NODES * D];
__device__ float g_Z[N_NODES * H];

// ---------------------------------------------------------------------------
// helpers
// ---------------------------------------------------------------------------
__device__ __forceinline__ void red_add_v4(float* p, float x, float y, float z, float w) {
    asm volatile("red.global.add.v4.f32 [%0], {%1, %2, %3, %4};"
                 :: "l"(p), "f"(x), "f"(y), "f"(z), "f"(w) : "memory");
}

// split a float2 into hi/lo packed f16x2 (hi + lo recovers ~22 mantissa bits)
__device__ __forceinline__ void split_f16x2(float2 v, unsigned& h, unsigned& l) {
    __half2 hb = __floats2half2_rn(v.x, v.y);
    float2 hf = __half22float2(hb);
    __half2 lb = __floats2half2_rn(v.x - hf.x, v.y - hf.y);
    h = *reinterpret_cast<unsigned*>(&hb);
    l = *reinterpret_cast<unsigned*>(&lb);
}

__device__ __forceinline__ unsigned pack_f16x2(float a, float b) {
    __half2 hb = __floats2half2_rn(a, b);
    return *reinterpret_cast<unsigned*>(&hb);
}

// D += A(f16) * B(f16), m16n8k16, f32 accumulate
__device__ __forceinline__ void mma_f16(float* c, const unsigned* a,
                                        unsigned b0, unsigned b1) {
    asm volatile(
        "mma.sync.aligned.m16n8k16.row.col.f32.f16.f16.f32 "
        "{%0,%1,%2,%3}, {%4,%5,%6,%7}, {%8,%9}, {%0,%1,%2,%3};"
        : "+f"(c[0]), "+f"(c[1]), "+f"(c[2]), "+f"(c[3])
        : "r"(a[0]), "r"(a[1]), "r"(a[2]), "r"(a[3]), "r"(b0), "r"(b1));
}

// ---------------------------------------------------------------------------
// K1: QKV projections via fp16-split tensor-core mma, 3-pass (hh + hl + lh;
// dropped ll ~2^-24 — effectively fp32-exact). One warp per 16 nodes.
// All 3 weight matrices staged in SMEM as pre-swizzled hi/lo f16 B-fragments.
// Also zeroes out[] rows and g_Z rows. N_NODES % 16 == 0.
// ---------------------------------------------------------------------------
__global__ __launch_bounds__(256) void proj_kernel(
    const float* __restrict__ x,
    const float* __restrict__ WQ,
    const float* __restrict__ WK,
    const float* __restrict__ WV,
    float* __restrict__ out)
{
    // [mat][ntile][kstep][lane] = (bh0, bh1, bl0, bl1)
    __shared__ uint4 sB[3][8][4][32];   // 48 KB

    const int tid = threadIdx.x;
    const float* Ws[3] = {WQ, WK, WV};
    for (int t = tid; t < 3 * 1024; t += 256) {
        int w = t >> 10, rem = t & 1023;
        int n = rem >> 7, k = (rem >> 5) & 3, l = rem & 31;
        int tig = l & 3, grp = l >> 2;
        int col = n * 8 + grp;
        int r0 = k * 16 + 2 * tig;
        const float* W = Ws[w];
        float2 w0 = make_float2(__ldg(&W[r0 * D + col]),       __ldg(&W[(r0 + 1) * D + col]));
        float2 w1 = make_float2(__ldg(&W[(r0 + 8) * D + col]), __ldg(&W[(r0 + 9) * D + col]));
        unsigned h0, l0, h1, l1;
        split_f16x2(w0, h0, l0);
        split_f16x2(w1, h1, l1);
        sB[w][n][k][l] = make_uint4(h0, h1, l0, l1);
    }
    __syncthreads();

    const int warp = tid >> 5;
    const int lane = tid & 31;
    const int tile = blockIdx.x * 8 + warp;     // 16-node tile index
    if (tile >= N_NODES / 16) return;

    const int grp = lane >> 2;    // 0..7
    const int tig = lane & 3;     // 0..3
    const long row0 = (long)tile * 16 + grp;
    const long row1 = row0 + 8;

    // --- A fragments from x (hi/lo fp16 split) ---
    unsigned Ah[4][4], Al[4][4];
#pragma unroll
    for (int k = 0; k < 4; k++) {
        float2 x0 = __ldg(reinterpret_cast<const float2*>(x + row0 * D + k * 16 + 2 * tig));
        float2 x1 = __ldg(reinterpret_cast<const float2*>(x + row1 * D + k * 16 + 2 * tig));
        float2 x2 = __ldg(reinterpret_cast<const float2*>(x + row0 * D + k * 16 + 8 + 2 * tig));
        float2 x3 = __ldg(reinterpret_cast<const float2*>(x + row1 * D + k * 16 + 8 + 2 * tig));
        split_f16x2(x0, Ah[k][0], Al[k][0]);
        split_f16x2(x1, Ah[k][1], Al[k][1]);
        split_f16x2(x2, Ah[k][2], Al[k][2]);
        split_f16x2(x3, Ah[k][3], Al[k][3]);
    }

    float* Outs[3] = {g_Q, g_K, g_V};
#pragma unroll
    for (int w = 0; w < 3; w++) {
        float* O = Outs[w];
#pragma unroll
        for (int n = 0; n < 8; n++) {
            uint4 b[4];
#pragma unroll
            for (int k = 0; k < 4; k++) b[k] = sB[w][n][k][lane];

            float c1[4] = {0.f, 0.f, 0.f, 0.f};
            float c2[4] = {0.f, 0.f, 0.f, 0.f};
            float c3[4] = {0.f, 0.f, 0.f, 0.f};
#pragma unroll
            for (int k = 0; k < 4; k++) {
                mma_f16(c1, Ah[k], b[k].x, b[k].y);   // hh
                mma_f16(c2, Ah[k], b[k].z, b[k].w);   // h*l
                mma_f16(c3, Al[k], b[k].x, b[k].y);   // l*h
            }

            int cc = n * 8 + 2 * tig;
            *reinterpret_cast<float2*>(&O[row0 * D + cc]) =
                make_float2(c1[0] + c2[0] + c3[0], c1[1] + c2[1] + c3[1]);
            *reinterpret_cast<float2*>(&O[row1 * D + cc]) =
                make_float2(c1[2] + c2[2] + c3[2], c1[3] + c2[3] + c3[3]);
        }
    }

    // --- zero accumulators for these 16 nodes ---
    float4 z4 = make_float4(0.f, 0.f, 0.f, 0.f);
    float4* o4 = reinterpret_cast<float4*>(out) + (long)tile * 256;  // 16 rows * 16 f4
#pragma unroll
    for (int i = 0; i < 8; i++) o4[i * 32 + lane] = z4;
    reinterpret_cast<float4*>(g_Z)[(long)tile * 32 + lane] = z4;
}

// ---------------------------------------------------------------------------
// K2: FUSED edge kernel. Per warp = 16 edges.
//  Phase A: Ef tile = ea[16x64] @ WE via fp16 2-pass split mma:
//           (Ah + Al) x fp16(WE) — 64 m16n8k16 per warp-tile.
//           Error ~2^-12 on Ef only (enters score via exp; cancels in ratio).
//  Phase B: 16 lanes/edge (lane g owns cols 4g..4g+3, head g>>1),
//           Ef from SMEM, K/Q/V gathered from L2,
//           score -> red.add.v4 scatter + Z atomic.
// NEDGES % 16 == 0 -> every live warp-tile is full.
// ---------------------------------------------------------------------------
__global__ __launch_bounds__(256) void fused_edge_kernel(
    const float* __restrict__ ea,
    const float* __restrict__ WE,
    const int* __restrict__ ei,
    float* __restrict__ out)
{
    // B fragments (fp16 hi only): [ntile][kstep][lane] = (bh0, bh1)
    __shared__ uint2 sB[8][4][32];     // 8 KB
    __shared__ float sEf[8][16][64];   // 32 KB (per-warp 16x64 Ef tiles)

    const int tid = threadIdx.x;

    // --- stage WE as packed fp16 B-fragments ---
    for (int t = tid; t < 1024; t += 256) {
        int n = t >> 7, k = (t >> 5) & 3, l = t & 31;
        int tig = l & 3, grp = l >> 2;
        int col = n * 8 + grp;
        int r0 = k * 16 + 2 * tig;
        unsigned b0 = pack_f16x2(__ldg(&WE[r0 * D + col]),       __ldg(&WE[(r0 + 1) * D + col]));
        unsigned b1 = pack_f16x2(__ldg(&WE[(r0 + 8) * D + col]), __ldg(&WE[(r0 + 9) * D + col]));
        sB[n][k][l] = make_uint2(b0, b1);
    }
    __syncthreads();

    const int warp = tid >> 5;
    const int lane = tid & 31;
    const int base = (blockIdx.x * 8 + warp) * 16;
    if (base >= NEDGES) return;   // tail warps (only block-wide sync is above)

    // --- preload src (lanes 0-15) / dst (lanes 16-31) for the 16 edges ---
    int sd = __ldg(&ei[(lane >> 4) * NEDGES + base + (lane & 15)]);

    const int grp = lane >> 2;    // 0..7  (row within tile)
    const int tig = lane & 3;     // 0..3  (col pair)
    const long row0 = base + grp;
    const long row1 = row0 + 8;

    // --- A fragments (16 x LDG.64), fp16 hi/lo split ---
    unsigned Ah[4][4], Al[4][4];
#pragma unroll
    for (int k = 0; k < 4; k++) {
        float2 x0 = __ldg(reinterpret_cast<const float2*>(ea + row0 * D + k * 16 + 2 * tig));
        float2 x1 = __ldg(reinterpret_cast<const float2*>(ea + row1 * D + k * 16 + 2 * tig));
        float2 x2 = __ldg(reinterpret_cast<const float2*>(ea + row0 * D + k * 16 + 8 + 2 * tig));
        float2 x3 = __ldg(reinterpret_cast<const float2*>(ea + row1 * D + k * 16 + 8 + 2 * tig));
        split_f16x2(x0, Ah[k][0], Al[k][0]);
        split_f16x2(x1, Ah[k][1], Al[k][1]);
        split_f16x2(x2, Ah[k][2], Al[k][2]);
        split_f16x2(x3, Ah[k][3], Al[k][3]);
    }

    // --- 8 n-tiles: 8 mma each, 2 independent accumulator chains ---
    const int swz = (grp & 7) << 3;   // XOR swizzle (consistent for row, row+8)
#pragma unroll
    for (int n = 0; n < 8; n++) {
        uint2 b[4];
#pragma unroll
        for (int k = 0; k < 4; k++) b[k] = sB[n][k][lane];

        float c1[4] = {0.f, 0.f, 0.f, 0.f};
        float c2[4] = {0.f, 0.f, 0.f, 0.f};
#pragma unroll
        for (int k = 0; k < 4; k++) {
            mma_f16(c1, Ah[k], b[k].x, b[k].y);   // hi x W
            mma_f16(c2, Al[k], b[k].x, b[k].y);   // lo x W
        }

        int colw = (8 * n + 2 * tig) ^ swz;
        *reinterpret_cast<float2*>(&sEf[warp][grp][colw]) =
            make_float2(c1[0] + c2[0], c1[1] + c2[1]);
        *reinterpret_cast<float2*>(&sEf[warp][grp + 8][colw]) =
            make_float2(c1[2] + c2[2], c1[3] + c2[3]);
    }
    __syncwarp();

    // --- edge phase: two half-warps, 8 iterations, 16 lanes per edge ---
    const int half = lane >> 4;
    const int g = lane & 15;
#pragma unroll
    for (int it = 0; it < 8; it++) {
        int r = it * 2 + half;
        int s = __shfl_sync(0xFFFFFFFFu, sd, r);
        int d = __shfl_sync(0xFFFFFFFFu, sd, 16 + r);

        float4 ef = *reinterpret_cast<const float4*>(
            &sEf[warp][r][(4 * g) ^ ((r & 7) << 3)]);
        float4 kk = *reinterpret_cast<const float4*>(&g_K[s * D + 4 * g]);
        float4 qq = *reinterpret_cast<const float4*>(&g_Q[d * D + 4 * g]);
        float4 vv = *reinterpret_cast<const float4*>(&g_V[s * D + 4 * g]);

        float p = (kk.x * qq.x) * ef.x;
        p = fmaf(kk.y * qq.y, ef.y, p);
        p = fmaf(kk.z * qq.z, ef.z, p);
        p = fmaf(kk.w * qq.w, ef.w, p);
        p += __shfl_xor_sync(0xFFFFFFFFu, p, 1);   // pair covers the head's 8 cols

        float sv = p * 0.35355339059327376f;       // 1/sqrt(8)
        sv = fminf(5.0f, fmaxf(-5.0f, sv));
        float sc = __expf(sv);

        red_add_v4(&out[(long)d * D + 4 * g],
                   vv.x * sc, vv.y * sc, vv.z * sc, vv.w * sc);
        if ((g & 1) == 0)
            atomicAdd(&g_Z[d * H + (g >> 1)], sc);
    }
}

// ---------------------------------------------------------------------------
// K3: out = wV / (Z + 1e-6)   (one float4 per thread)
// ---------------------------------------------------------------------------
__global__ void div_kernel(float4* __restrict__ out4) {
    int i = blockIdx.x * blockDim.x + threadIdx.x;
    if (i >= (N_NODES * D) / 4) return;
    int n  = i >> 4;           // 16 float4 per node
    int c4 = i & 15;
    int h  = c4 >> 1;          // head = (4*c4)/8
    float r = 1.0f / (g_Z[n * H + h] + 1e-6f);
    float4 v = out4[i];
    v.x *= r; v.y *= r; v.z *= r; v.w *= r;
    out4[i] = v;
}

// ---------------------------------------------------------------------------
extern "C" void kernel_launch(void* const* d_in, const int* in_sizes, int n_in,
                              void* d_out, int out_size)
{
    const float* x   = (const float*)d_in[0];
    const float* ea  = (const float*)d_in[1];
    const float* WQ  = (const float*)d_in[2];
    const float* WK  = (const float*)d_in[3];
    const float* WV  = (const float*)d_in[4];
    const float* WE  = (const float*)d_in[5];
    const int*   ei  = (const int*)d_in[6];
    float* out = (float*)d_out;

    (void)in_sizes; (void)n_in; (void)out_size;

    proj_kernel<<<(N_NODES / 16 + 7) / 8, 256>>>(x, WQ, WK, WV, out);
    fused_edge_kernel<<<(NEDGES / 16 + 7) / 8, 256>>>(ea, WE, ei, out);
    div_kernel<<<(N_NODES * D / 4 + 255) / 256, 256>>>((float4*)out);
}

// round 7
// speedup vs baseline: 2.5732x; 1.0670x over previous
#include <cuda_runtime.h>
#include <cuda_fp16.h>

#define N_NODES 100000
#define NEDGES  1250000
#define D       64
#define H       8
// DH = 8, scale = 1/sqrt(8)

// Scratch (static __device__ arrays: allocation-free per harness rules)
__device__ float g_Q[N_NODES * D];
__device__ float g_K[N_NODES * D];
__device__ float g_V[N_NODES * D];
__device__ float g_Z[N_NODES * H];

// ---------------------------------------------------------------------------
// helpers
// ---------------------------------------------------------------------------
__device__ __forceinline__ void red_add_v4(float* p, float x, float y, float z, float w) {
    asm volatile("red.global.add.v4.f32 [%0], {%1, %2, %3, %4};"
                 :: "l"(p), "f"(x), "f"(y), "f"(z), "f"(w) : "memory");
}

// split a float2 into hi/lo packed f16x2 (hi + lo recovers ~22 mantissa bits)
__device__ __forceinline__ void split_f16x2(float2 v, unsigned& h, unsigned& l) {
    __half2 hb = __floats2half2_rn(v.x, v.y);
    float2 hf = __half22float2(hb);
    __half2 lb = __floats2half2_rn(v.x - hf.x, v.y - hf.y);
    h = *reinterpret_cast<unsigned*>(&hb);
    l = *reinterpret_cast<unsigned*>(&lb);
}

__device__ __forceinline__ unsigned pack_f16x2(float a, float b) {
    __half2 hb = __floats2half2_rn(a, b);
    return *reinterpret_cast<unsigned*>(&hb);
}

// D += A(f16) * B(f16), m16n8k16, f32 accumulate
__device__ __forceinline__ void mma_f16(float* c, const unsigned* a,
                                        unsigned b0, unsigned b1) {
    asm volatile(
        "mma.sync.aligned.m16n8k16.row.col.f32.f16.f16.f32 "
        "{%0,%1,%2,%3}, {%4,%5,%6,%7}, {%8,%9}, {%0,%1,%2,%3};"
        : "+f"(c[0]), "+f"(c[1]), "+f"(c[2]), "+f"(c[3])
        : "r"(a[0]), "r"(a[1]), "r"(a[2]), "r"(a[3]), "r"(b0), "r"(b1));
}

// ---------------------------------------------------------------------------
// K1: QKV projections via fp16-split tensor-core mma, 3-pass (hh + hl + lh;
// dropped ll ~2^-24 — effectively fp32-exact). One warp per 16 nodes.
// Also zeroes out[] rows and g_Z rows. N_NODES % 16 == 0.
// ---------------------------------------------------------------------------
__global__ __launch_bounds__(256) void proj_kernel(
    const float* __restrict__ x,
    const float* __restrict__ WQ,
    const float* __restrict__ WK,
    const float* __restrict__ WV,
    float* __restrict__ out)
{
    // [mat][ntile][kstep][lane] = (bh0, bh1, bl0, bl1)
    __shared__ uint4 sB[3][8][4][32];   // 48 KB

    const int tid = threadIdx.x;
    const float* Ws[3] = {WQ, WK, WV};
    for (int t = tid; t < 3 * 1024; t += 256) {
        int w = t >> 10, rem = t & 1023;
        int n = rem >> 7, k = (rem >> 5) & 3, l = rem & 31;
        int tig = l & 3, grp = l >> 2;
        int col = n * 8 + grp;
        int r0 = k * 16 + 2 * tig;
        const float* W = Ws[w];
        float2 w0 = make_float2(__ldg(&W[r0 * D + col]),       __ldg(&W[(r0 + 1) * D + col]));
        float2 w1 = make_float2(__ldg(&W[(r0 + 8) * D + col]), __ldg(&W[(r0 + 9) * D + col]));
        unsigned h0, l0, h1, l1;
        split_f16x2(w0, h0, l0);
        split_f16x2(w1, h1, l1);
        sB[w][n][k][l] = make_uint4(h0, h1, l0, l1);
    }
    __syncthreads();

    const int warp = tid >> 5;
    const int lane = tid & 31;
    const int tile = blockIdx.x * 8 + warp;     // 16-node tile index
    if (tile >= N_NODES / 16) return;

    const int grp = lane >> 2;    // 0..7
    const int tig = lane & 3;     // 0..3
    const long row0 = (long)tile * 16 + grp;
    const long row1 = row0 + 8;

    // --- A fragments from x (hi/lo fp16 split) ---
    unsigned Ah[4][4], Al[4][4];
#pragma unroll
    for (int k = 0; k < 4; k++) {
        float2 x0 = __ldg(reinterpret_cast<const float2*>(x + row0 * D + k * 16 + 2 * tig));
        float2 x1 = __ldg(reinterpret_cast<const float2*>(x + row1 * D + k * 16 + 2 * tig));
        float2 x2 = __ldg(reinterpret_cast<const float2*>(x + row0 * D + k * 16 + 8 + 2 * tig));
        float2 x3 = __ldg(reinterpret_cast<const float2*>(x + row1 * D + k * 16 + 8 + 2 * tig));
        split_f16x2(x0, Ah[k][0], Al[k][0]);
        split_f16x2(x1, Ah[k][1], Al[k][1]);
        split_f16x2(x2, Ah[k][2], Al[k][2]);
        split_f16x2(x3, Ah[k][3], Al[k][3]);
    }

    float* Outs[3] = {g_Q, g_K, g_V};
#pragma unroll
    for (int w = 0; w < 3; w++) {
        float* O = Outs[w];
#pragma unroll
        for (int n = 0; n < 8; n++) {
            uint4 b[4];
#pragma unroll
            for (int k = 0; k < 4; k++) b[k] = sB[w][n][k][lane];

            float c1[4] = {0.f, 0.f, 0.f, 0.f};
            float c2[4] = {0.f, 0.f, 0.f, 0.f};
            float c3[4] = {0.f, 0.f, 0.f, 0.f};
#pragma unroll
            for (int k = 0; k < 4; k++) {
                mma_f16(c1, Ah[k], b[k].x, b[k].y);   // hh
                mma_f16(c2, Ah[k], b[k].z, b[k].w);   // h*l
                mma_f16(c3, Al[k], b[k].x, b[k].y);   // l*h
            }

            int cc = n * 8 + 2 * tig;
            *reinterpret_cast<float2*>(&O[row0 * D + cc]) =
                make_float2(c1[0] + c2[0] + c3[0], c1[1] + c2[1] + c3[1]);
            *reinterpret_cast<float2*>(&O[row1 * D + cc]) =
                make_float2(c1[2] + c2[2] + c3[2], c1[3] + c2[3] + c3[3]);
        }
    }

    // --- zero accumulators for these 16 nodes ---
    float4 z4 = make_float4(0.f, 0.f, 0.f, 0.f);
    float4* o4 = reinterpret_cast<float4*>(out) + (long)tile * 256;  // 16 rows * 16 f4
#pragma unroll
    for (int i = 0; i < 8; i++) o4[i * 32 + lane] = z4;
    reinterpret_cast<float4*>(g_Z)[(long)tile * 32 + lane] = z4;
}

// ---------------------------------------------------------------------------
// K2: FUSED edge kernel. Per warp = 16 edges.
//  Phase A: Ef tile = ea[16x64] @ WE via fp16 2-pass split mma
//           ((Ah + Al) x fp16(WE)), 64 m16n8k16 per warp-tile -> SMEM.
//  Phase B: 16 lanes/edge, software-pipelined: iteration-0 K/Q/V gathers
//           issued BEFORE the mma loop (latency hidden under tensor work),
//           each iteration prefetches the next one's gathers.
//  ea is read with __ldcs (evict-first) so L2 keeps Q/K/V resident.
// NEDGES % 16 == 0 -> every live warp-tile is full.
// ---------------------------------------------------------------------------
__global__ __launch_bounds__(256) void fused_edge_kernel(
    const float* __restrict__ ea,
    const float* __restrict__ WE,
    const int* __restrict__ ei,
    float* __restrict__ out)
{
    // B fragments (fp16): [ntile][kstep][lane] = (bh0, bh1)
    __shared__ uint2 sB[8][4][32];     // 8 KB
    __shared__ float sEf[8][16][64];   // 32 KB (per-warp 16x64 Ef tiles)

    const int tid = threadIdx.x;

    // --- stage WE as packed fp16 B-fragments ---
    for (int t = tid; t < 1024; t += 256) {
        int n = t >> 7, k = (t >> 5) & 3, l = t & 31;
        int tig = l & 3, grp = l >> 2;
        int col = n * 8 + grp;
        int r0 = k * 16 + 2 * tig;
        unsigned b0 = pack_f16x2(__ldg(&WE[r0 * D + col]),       __ldg(&WE[(r0 + 1) * D + col]));
        unsigned b1 = pack_f16x2(__ldg(&WE[(r0 + 8) * D + col]), __ldg(&WE[(r0 + 9) * D + col]));
        sB[n][k][l] = make_uint2(b0, b1);
    }
    __syncthreads();

    const int warp = tid >> 5;
    const int lane = tid & 31;
    const int base = (blockIdx.x * 8 + warp) * 16;
    if (base >= NEDGES) return;   // tail warps (only block-wide sync is above)

    // --- edge indices: lanes 0-15 hold src, lanes 16-31 hold dst ---
    int sd = __ldg(&ei[(lane >> 4) * NEDGES + base + (lane & 15)]);

    const int half = lane >> 4;
    const int g    = lane & 15;

    // --- issue iteration-0 gathers NOW: latency hides under the mma loop ---
    int s_cur = __shfl_sync(0xFFFFFFFFu, sd, half);
    int d_cur = __shfl_sync(0xFFFFFFFFu, sd, 16 + half);
    float4 kk = __ldg(reinterpret_cast<const float4*>(&g_K[(long)s_cur * D + 4 * g]));
    float4 qq = __ldg(reinterpret_cast<const float4*>(&g_Q[(long)d_cur * D + 4 * g]));
    float4 vv = __ldg(reinterpret_cast<const float4*>(&g_V[(long)s_cur * D + 4 * g]));

    const int grp = lane >> 2;    // 0..7  (row within tile)
    const int tig = lane & 3;     // 0..3  (col pair)
    const long row0 = base + grp;
    const long row1 = row0 + 8;

    // --- A fragments (16 x LDG.64, evict-first), fp16 hi/lo split ---
    unsigned Ah[4][4], Al[4][4];
#pragma unroll
    for (int k = 0; k < 4; k++) {
        float2 x0 = __ldcs(reinterpret_cast<const float2*>(ea + row0 * D + k * 16 + 2 * tig));
        float2 x1 = __ldcs(reinterpret_cast<const float2*>(ea + row1 * D + k * 16 + 2 * tig));
        float2 x2 = __ldcs(reinterpret_cast<const float2*>(ea + row0 * D + k * 16 + 8 + 2 * tig));
        float2 x3 = __ldcs(reinterpret_cast<const float2*>(ea + row1 * D + k * 16 + 8 + 2 * tig));
        split_f16x2(x0, Ah[k][0], Al[k][0]);
        split_f16x2(x1, Ah[k][1], Al[k][1]);
        split_f16x2(x2, Ah[k][2], Al[k][2]);
        split_f16x2(x3, Ah[k][3], Al[k][3]);
    }

    // --- 8 n-tiles: 8 mma each, 2 independent accumulator chains ---
    const int swz = (grp & 7) << 3;   // XOR swizzle (consistent for row, row+8)
#pragma unroll
    for (int n = 0; n < 8; n++) {
        uint2 b[4];
#pragma unroll
        for (int k = 0; k < 4; k++) b[k] = sB[n][k][lane];

        float c1[4] = {0.f, 0.f, 0.f, 0.f};
        float c2[4] = {0.f, 0.f, 0.f, 0.f};
#pragma unroll
        for (int k = 0; k < 4; k++) {
            mma_f16(c1, Ah[k], b[k].x, b[k].y);   // hi x W
            mma_f16(c2, Al[k], b[k].x, b[k].y);   // lo x W
        }

        int colw = (8 * n + 2 * tig) ^ swz;
        *reinterpret_cast<float2*>(&sEf[warp][grp][colw]) =
            make_float2(c1[0] + c2[0], c1[1] + c2[1]);
        *reinterpret_cast<float2*>(&sEf[warp][grp + 8][colw]) =
            make_float2(c1[2] + c2[2], c1[3] + c2[3]);
    }
    __syncwarp();

    // --- edge phase: software-pipelined, 8 iterations, 16 lanes per edge ---
#pragma unroll
    for (int it = 0; it < 8; it++) {
        // prefetch next iteration's gathers (in flight during this compute)
        int s_nxt = 0, d_nxt = 0;
        float4 kk_n, qq_n, vv_n;
        if (it < 7) {
            s_nxt = __shfl_sync(0xFFFFFFFFu, sd, (it + 1) * 2 + half);
            d_nxt = __shfl_sync(0xFFFFFFFFu, sd, 16 + (it + 1) * 2 + half);
            kk_n = __ldg(reinterpret_cast<const float4*>(&g_K[(long)s_nxt * D + 4 * g]));
            qq_n = __ldg(reinterpret_cast<const float4*>(&g_Q[(long)d_nxt * D + 4 * g]));
            vv_n = __ldg(reinterpret_cast<const float4*>(&g_V[(long)s_nxt * D + 4 * g]));
        }

        int r = it * 2 + half;
        float4 ef = *reinterpret_cast<const float4*>(
            &sEf[warp][r][(4 * g) ^ ((r & 7) << 3)]);

        float p = (kk.x * qq.x) * ef.x;
        p = fmaf(kk.y * qq.y, ef.y, p);
        p = fmaf(kk.z * qq.z, ef.z, p);
        p = fmaf(kk.w * qq.w, ef.w, p);
        p += __shfl_xor_sync(0xFFFFFFFFu, p, 1);   // pair covers the head's 8 cols

        float sv = p * 0.35355339059327376f;       // 1/sqrt(8)
        sv = fminf(5.0f, fmaxf(-5.0f, sv));
        float sc = __expf(sv);

        red_add_v4(&out[(long)d_cur * D + 4 * g],
                   vv.x * sc, vv.y * sc, vv.z * sc, vv.w * sc);
        if ((g & 1) == 0)
            atomicAdd(&g_Z[d_cur * H + (g >> 1)], sc);

        kk = kk_n; qq = qq_n; vv = vv_n;
        s_cur = s_nxt; d_cur = d_nxt;
    }
}

// ---------------------------------------------------------------------------
// K3: out = wV / (Z + 1e-6)   (one float4 per thread)
// ---------------------------------------------------------------------------
__global__ void div_kernel(float4* __restrict__ out4) {
    int i = blockIdx.x * blockDim.x + threadIdx.x;
    if (i >= (N_NODES * D) / 4) return;
    int n  = i >> 4;           // 16 float4 per node
    int c4 = i & 15;
    int h  = c4 >> 1;          // head = (4*c4)/8
    float r = 1.0f / (g_Z[n * H + h] + 1e-6f);
    float4 v = out4[i];
    v.x *= r; v.y *= r; v.z *= r; v.w *= r;
    out4[i] = v;
}

// ---------------------------------------------------------------------------
extern "C" void kernel_launch(void* const* d_in, const int* in_sizes, int n_in,
                              void* d_out, int out_size)
{
    const float* x   = (const float*)d_in[0];
    const float* ea  = (const float*)d_in[1];
    const float* WQ  = (const float*)d_in[2];
    const float* WK  = (const float*)d_in[3];
    const float* WV  = (const float*)d_in[4];
    const float* WE  = (const float*)d_in[5];
    const int*   ei  = (const int*)d_in[6];
    float* out = (float*)d_out;

    (void)in_sizes; (void)n_in; (void)out_size;

    proj_kernel<<<(N_NODES / 16 + 7) / 8, 256>>>(x, WQ, WK, WV, out);
    fused_edge_kernel<<<(NEDGES / 16 + 7) / 8, 256>>>(ea, WE, ei, out);
    div_kernel<<<(N_NODES * D / 4 + 255) / 256, 256>>>((float4*)out);
}

// round 8
// speedup vs baseline: 2.6788x; 1.0411x over previous
#include <cuda_runtime.h>
#include <cuda_fp16.h>

#define N_NODES 100000
#define NEDGES  1250000
#define D       64
#define H       8
// DH = 8, scale = 1/sqrt(8)

// Scratch (static __device__ arrays: allocation-free per harness rules)
__device__ float g_Q[N_NODES * D];
__device__ float g_K[N_NODES * D];
__device__ float g_V[N_NODES * D];
__device__ float g_Z[N_NODES * H];

// ---------------------------------------------------------------------------
// helpers
// ---------------------------------------------------------------------------
__device__ __forceinline__ void red_add_v4(float* p, float x, float y, float z, float w) {
    asm volatile("red.global.add.v4.f32 [%0], {%1, %2, %3, %4};"
                 :: "l"(p), "f"(x), "f"(y), "f"(z), "f"(w) : "memory");
}

// split a float2 into hi/lo packed f16x2 (hi + lo recovers ~22 mantissa bits)
__device__ __forceinline__ void split_f16x2(float2 v, unsigned& h, unsigned& l) {
    __half2 hb = __floats2half2_rn(v.x, v.y);
    float2 hf = __half22float2(hb);
    __half2 lb = __floats2half2_rn(v.x - hf.x, v.y - hf.y);
    h = *reinterpret_cast<unsigned*>(&hb);
    l = *reinterpret_cast<unsigned*>(&lb);
}

__device__ __forceinline__ unsigned pack_f16x2(float a, float b) {
    __half2 hb = __floats2half2_rn(a, b);
    return *reinterpret_cast<unsigned*>(&hb);
}

// D += A(f16) * B(f16), m16n8k16, f32 accumulate
__device__ __forceinline__ void mma_f16(float* c, const unsigned* a,
                                        unsigned b0, unsigned b1) {
    asm volatile(
        "mma.sync.aligned.m16n8k16.row.col.f32.f16.f16.f32 "
        "{%0,%1,%2,%3}, {%4,%5,%6,%7}, {%8,%9}, {%0,%1,%2,%3};"
        : "+f"(c[0]), "+f"(c[1]), "+f"(c[2]), "+f"(c[3])
        : "r"(a[0]), "r"(a[1]), "r"(a[2]), "r"(a[3]), "r"(b0), "r"(b1));
}

// ---------------------------------------------------------------------------
// K1: QKV projections via fp16-split tensor-core mma, 3-pass (hh + hl + lh;
// dropped ll ~2^-24 — effectively fp32-exact). One warp per 16 nodes.
// Also zeroes out[] rows and g_Z rows. N_NODES % 16 == 0.
// ---------------------------------------------------------------------------
__global__ __launch_bounds__(256) void proj_kernel(
    const float* __restrict__ x,
    const float* __restrict__ WQ,
    const float* __restrict__ WK,
    const float* __restrict__ WV,
    float* __restrict__ out)
{
    // [mat][ntile][kstep][lane] = (bh0, bh1, bl0, bl1)
    __shared__ uint4 sB[3][8][4][32];   // 48 KB

    const int tid = threadIdx.x;
    const float* Ws[3] = {WQ, WK, WV};
    for (int t = tid; t < 3 * 1024; t += 256) {
        int w = t >> 10, rem = t & 1023;
        int n = rem >> 7, k = (rem >> 5) & 3, l = rem & 31;
        int tig = l & 3, grp = l >> 2;
        int col = n * 8 + grp;
        int r0 = k * 16 + 2 * tig;
        const float* W = Ws[w];
        float2 w0 = make_float2(__ldg(&W[r0 * D + col]),       __ldg(&W[(r0 + 1) * D + col]));
        float2 w1 = make_float2(__ldg(&W[(r0 + 8) * D + col]), __ldg(&W[(r0 + 9) * D + col]));
        unsigned h0, l0, h1, l1;
        split_f16x2(w0, h0, l0);
        split_f16x2(w1, h1, l1);
        sB[w][n][k][l] = make_uint4(h0, h1, l0, l1);
    }
    __syncthreads();

    const int warp = tid >> 5;
    const int lane = tid & 31;
    const int tile = blockIdx.x * 8 + warp;     // 16-node tile index
    if (tile >= N_NODES / 16) return;

    const int grp = lane >> 2;    // 0..7
    const int tig = lane & 3;     // 0..3
    const long row0 = (long)tile * 16 + grp;
    const long row1 = row0 + 8;

    // --- A fragments from x (hi/lo fp16 split) ---
    unsigned Ah[4][4], Al[4][4];
#pragma unroll
    for (int k = 0; k < 4; k++) {
        float2 x0 = __ldg(reinterpret_cast<const float2*>(x + row0 * D + k * 16 + 2 * tig));
        float2 x1 = __ldg(reinterpret_cast<const float2*>(x + row1 * D + k * 16 + 2 * tig));
        float2 x2 = __ldg(reinterpret_cast<const float2*>(x + row0 * D + k * 16 + 8 + 2 * tig));
        float2 x3 = __ldg(reinterpret_cast<const float2*>(x + row1 * D + k * 16 + 8 + 2 * tig));
        split_f16x2(x0, Ah[k][0], Al[k][0]);
        split_f16x2(x1, Ah[k][1], Al[k][1]);
        split_f16x2(x2, Ah[k][2], Al[k][2]);
        split_f16x2(x3, Ah[k][3], Al[k][3]);
    }

    float* Outs[3] = {g_Q, g_K, g_V};
#pragma unroll
    for (int w = 0; w < 3; w++) {
        float* O = Outs[w];
#pragma unroll
        for (int n = 0; n < 8; n++) {
            uint4 b[4];
#pragma unroll
            for (int k = 0; k < 4; k++) b[k] = sB[w][n][k][lane];

            float c1[4] = {0.f, 0.f, 0.f, 0.f};
            float c2[4] = {0.f, 0.f, 0.f, 0.f};
            float c3[4] = {0.f, 0.f, 0.f, 0.f};
#pragma unroll
            for (int k = 0; k < 4; k++) {
                mma_f16(c1, Ah[k], b[k].x, b[k].y);   // hh
                mma_f16(c2, Ah[k], b[k].z, b[k].w);   // h*l
                mma_f16(c3, Al[k], b[k].x, b[k].y);   // l*h
            }

            int cc = n * 8 + 2 * tig;
            *reinterpret_cast<float2*>(&O[row0 * D + cc]) =
                make_float2(c1[0] + c2[0] + c3[0], c1[1] + c2[1] + c3[1]);
            *reinterpret_cast<float2*>(&O[row1 * D + cc]) =
                make_float2(c1[2] + c2[2] + c3[2], c1[3] + c2[3] + c3[3]);
        }
    }

    // --- zero accumulators for these 16 nodes ---
    float4 z4 = make_float4(0.f, 0.f, 0.f, 0.f);
    float4* o4 = reinterpret_cast<float4*>(out) + (long)tile * 256;  // 16 rows * 16 f4
#pragma unroll
    for (int i = 0; i < 8; i++) o4[i * 32 + lane] = z4;
    reinterpret_cast<float4*>(g_Z)[(long)tile * 32 + lane] = z4;
}

// ---------------------------------------------------------------------------
// K2: FUSED edge kernel. Per warp = 16 edges.
//  Phase A: Ef tile = ea[16x64] @ WE via fp16 2-pass split mma
//           ((Ah + Al) x fp16(WE)), 64 m16n8k16 per warp-tile -> SMEM.
//  Phase B: 16 lanes/edge, depth-2 software pipeline: K/Q gathers issued
//           2 iterations ahead (they head the dependency chain), V gathers
//           1 ahead; the first two batches are issued BEFORE the mma loop
//           so phase-A tensor work hides a full L2/DRAM round-trip.
//  ea is read with __ldcs (evict-first) so L2 keeps Q/K/V resident.
// NEDGES % 16 == 0 -> every live warp-tile is full.
// ---------------------------------------------------------------------------
__global__ __launch_bounds__(256) void fused_edge_kernel(
    const float* __restrict__ ea,
    const float* __restrict__ WE,
    const int* __restrict__ ei,
    float* __restrict__ out)
{
    // B fragments (fp16): [ntile][kstep][lane] = (bh0, bh1)
    __shared__ uint2 sB[8][4][32];     // 8 KB
    __shared__ float sEf[8][16][64];   // 32 KB (per-warp 16x64 Ef tiles)

    const int tid = threadIdx.x;

    // --- stage WE as packed fp16 B-fragments ---
    for (int t = tid; t < 1024; t += 256) {
        int n = t >> 7, k = (t >> 5) & 3, l = t & 31;
        int tig = l & 3, grp = l >> 2;
        int col = n * 8 + grp;
        int r0 = k * 16 + 2 * tig;
        unsigned b0 = pack_f16x2(__ldg(&WE[r0 * D + col]),       __ldg(&WE[(r0 + 1) * D + col]));
        unsigned b1 = pack_f16x2(__ldg(&WE[(r0 + 8) * D + col]), __ldg(&WE[(r0 + 9) * D + col]));
        sB[n][k][l] = make_uint2(b0, b1);
    }
    __syncthreads();

    const int warp = tid >> 5;
    const int lane = tid & 31;
    const int base = (blockIdx.x * 8 + warp) * 16;
    if (base >= NEDGES) return;   // tail warps (only block-wide sync is above)

    // --- edge indices: lanes 0-15 hold src, lanes 16-31 hold dst ---
    int sd = __ldg(&ei[(lane >> 4) * NEDGES + base + (lane & 15)]);

    const int half = lane >> 4;
    const int g    = lane & 15;

    // --- issue edge-0 and edge-1 gathers NOW (hidden under the mma loop) ---
    int s0 = __shfl_sync(0xFFFFFFFFu, sd, half);
    int d0 = __shfl_sync(0xFFFFFFFFu, sd, 16 + half);
    int s1 = __shfl_sync(0xFFFFFFFFu, sd, 2 + half);
    int d1 = __shfl_sync(0xFFFFFFFFu, sd, 18 + half);
    float4 kk0 = __ldg(reinterpret_cast<const float4*>(&g_K[(long)s0 * D + 4 * g]));
    float4 qq0 = __ldg(reinterpret_cast<const float4*>(&g_Q[(long)d0 * D + 4 * g]));
    float4 vv0 = __ldg(reinterpret_cast<const float4*>(&g_V[(long)s0 * D + 4 * g]));
    float4 kk1 = __ldg(reinterpret_cast<const float4*>(&g_K[(long)s1 * D + 4 * g]));
    float4 qq1 = __ldg(reinterpret_cast<const float4*>(&g_Q[(long)d1 * D + 4 * g]));

    const int grp = lane >> 2;    // 0..7  (row within tile)
    const int tig = lane & 3;     // 0..3  (col pair)
    const long row0 = base + grp;
    const long row1 = row0 + 8;

    // --- A fragments (16 x LDG.64, evict-first), fp16 hi/lo split ---
    unsigned Ah[4][4], Al[4][4];
#pragma unroll
    for (int k = 0; k < 4; k++) {
        float2 x0 = __ldcs(reinterpret_cast<const float2*>(ea + row0 * D + k * 16 + 2 * tig));
        float2 x1 = __ldcs(reinterpret_cast<const float2*>(ea + row1 * D + k * 16 + 2 * tig));
        float2 x2 = __ldcs(reinterpret_cast<const float2*>(ea + row0 * D + k * 16 + 8 + 2 * tig));
        float2 x3 = __ldcs(reinterpret_cast<const float2*>(ea + row1 * D + k * 16 + 8 + 2 * tig));
        split_f16x2(x0, Ah[k][0], Al[k][0]);
        split_f16x2(x1, Ah[k][1], Al[k][1]);
        split_f16x2(x2, Ah[k][2], Al[k][2]);
        split_f16x2(x3, Ah[k][3], Al[k][3]);
    }

    // --- 8 n-tiles: 8 mma each, 2 independent accumulator chains ---
    const int swz = (grp & 7) << 3;   // XOR swizzle (consistent for row, row+8)
#pragma unroll
    for (int n = 0; n < 8; n++) {
        uint2 b[4];
#pragma unroll
        for (int k = 0; k < 4; k++) b[k] = sB[n][k][lane];

        float c1[4] = {0.f, 0.f, 0.f, 0.f};
        float c2[4] = {0.f, 0.f, 0.f, 0.f};
#pragma unroll
        for (int k = 0; k < 4; k++) {
            mma_f16(c1, Ah[k], b[k].x, b[k].y);   // hi x W
            mma_f16(c2, Al[k], b[k].x, b[k].y);   // lo x W
        }

        int colw = (8 * n + 2 * tig) ^ swz;
        *reinterpret_cast<float2*>(&sEf[warp][grp][colw]) =
            make_float2(c1[0] + c2[0], c1[1] + c2[1]);
        *reinterpret_cast<float2*>(&sEf[warp][grp + 8][colw]) =
            make_float2(c1[2] + c2[2], c1[3] + c2[3]);
    }
    __syncwarp();

    // --- edge phase: depth-2 (kk/qq) + depth-1 (vv) pipeline, 8 iterations ---
    int s2, d2;
    float4 kk2, qq2, vv1;
#pragma unroll
    for (int it = 0; it < 8; it++) {
        if (it < 7)
            vv1 = __ldg(reinterpret_cast<const float4*>(&g_V[(long)s1 * D + 4 * g]));
        if (it < 6) {
            s2 = __shfl_sync(0xFFFFFFFFu, sd, (it + 2) * 2 + half);
            d2 = __shfl_sync(0xFFFFFFFFu, sd, 16 + (it + 2) * 2 + half);
            kk2 = __ldg(reinterpret_cast<const float4*>(&g_K[(long)s2 * D + 4 * g]));
            qq2 = __ldg(reinterpret_cast<const float4*>(&g_Q[(long)d2 * D + 4 * g]));
        }

        int r = it * 2 + half;
        float4 ef = *reinterpret_cast<const float4*>(
            &sEf[warp][r][(4 * g) ^ ((r & 7) << 3)]);

        float p = (kk0.x * qq0.x) * ef.x;
        p = fmaf(kk0.y * qq0.y, ef.y, p);
        p = fmaf(kk0.z * qq0.z, ef.z, p);
        p = fmaf(kk0.w * qq0.w, ef.w, p);
        p += __shfl_xor_sync(0xFFFFFFFFu, p, 1);   // pair covers the head's 8 cols

        // clamp in p-domain (+-5*sqrt(8)); exp(x/sqrt(8)) = 2^(x*log2e/sqrt(8))
        float sv = fminf(14.142135623730951f, fmaxf(-14.142135623730951f, p));
        float sc = exp2f(sv * 0.51002501915290554f);

        red_add_v4(&out[(long)d0 * D + 4 * g],
                   vv0.x * sc, vv0.y * sc, vv0.z * sc, vv0.w * sc);
        if ((g & 1) == 0)
            atomicAdd(&g_Z[d0 * H + (g >> 1)], sc);

        // rotate pipeline
        kk0 = kk1; qq0 = qq1; vv0 = vv1; s0 = s1; d0 = d1;
        kk1 = kk2; qq1 = qq2; s1 = s2; d1 = d2;
    }
}

// ---------------------------------------------------------------------------
// K3: out = wV / (Z + 1e-6)   (one float4 per thread)
// ---------------------------------------------------------------------------
__global__ void div_kernel(float4* __restrict__ out4) {
    int i = blockIdx.x * blockDim.x + threadIdx.x;
    if (i >= (N_NODES * D) / 4) return;
    int n  = i >> 4;           // 16 float4 per node
    int c4 = i & 15;
    int h  = c4 >> 1;          // head = (4*c4)/8
    float r = 1.0f / (g_Z[n * H + h] + 1e-6f);
    float4 v = out4[i];
    v.x *= r; v.y *= r; v.z *= r; v.w *= r;
    out4[i] = v;
}

// ---------------------------------------------------------------------------
extern "C" void kernel_launch(void* const* d_in, const int* in_sizes, int n_in,
                              void* d_out, int out_size)
{
    const float* x   = (const float*)d_in[0];
    const float* ea  = (const float*)d_in[1];
    const float* WQ  = (const float*)d_in[2];
    const float* WK  = (const float*)d_in[3];
    const float* WV  = (const float*)d_in[4];
    const float* WE  = (const float*)d_in[5];
    const int*   ei  = (const int*)d_in[6];
    float* out = (float*)d_out;

    (void)in_sizes; (void)n_in; (void)out_size;

    proj_kernel<<<(N_NODES / 16 + 7) / 8, 256>>>(x, WQ, WK, WV, out);
    fused_edge_kernel<<<(NEDGES / 16 + 7) / 8, 256>>>(ea, WE, ei, out);
    div_kernel<<<(N_NODES * D / 4 + 255) / 256, 256>>>((float4*)out);
}